// round 12
// baseline (speedup 1.0000x reference)
#include <cuda_runtime.h>
#include <math.h>

#define BB 64
#define PP 256
#define NN 4096
#define SPLITK 64
#define KC (NN / SPLITK)   // 64 (two 32-k chunks per block)
#define KCH 32
#define SPLITP 8
#define PCH (PP / SPLITP)  // 32 (one chunk per block)

typedef unsigned long long ull;

// Interleaved (cos, sin) tables
__device__ __align__(16) float2 g_csphi[BB * NN];
__device__ __align__(16) float2 g_csxi[PP * NN];
__device__ float g_mpart[SPLITK * BB * PP];
__device__ float g_w[BB * PP];
__device__ __align__(16) ull g_cpart[SPLITP][BB * NN];  // packed (Wc, Ws) partials

// Packed fp32x2 FMA (Blackwell FFMA2)
__device__ __forceinline__ ull ffma2(ull a, ull b, ull c) {
    ull d;
    asm("fma.rn.f32x2 %0, %1, %2, %3;" : "=l"(d) : "l"(a), "l"(b), "l"(c));
    return d;
}
__device__ __forceinline__ ull pack2(float x, float y) {
    ull r; asm("mov.b64 %0, {%1, %2};" : "=l"(r) : "f"(x), "f"(y)); return r;
}
__device__ __forceinline__ float2 unpack2(ull v) {
    float2 f; asm("mov.b64 {%0, %1}, %2;" : "=f"(f.x), "=f"(f.y) : "l"(v)); return f;
}

// ---------------------------------------------------------------------------
// Kernel 1: trig tables, interleaved (cos, sin). MUFU fast path (__sincosf):
// args are in [0, 2*pi), abs err ~3e-6 — far inside the 1e-3 tolerance.
// ---------------------------------------------------------------------------
__global__ __launch_bounds__(256) void trig_kernel(const float* __restrict__ phi,
                                                   const float* __restrict__ xi) {
    int i = blockIdx.x * 256 + threadIdx.x;
    if (i < BB * NN) {
        float s, c;
        __sincosf(phi[i], &s, &c);
        g_csphi[i] = make_float2(c, s);
    } else if (i < (BB + PP) * NN) {
        int j = i - BB * NN;
        float s, c;
        __sincosf(xi[j], &s, &c);
        g_csxi[j] = make_float2(c, s);
    }
}

// ---------------------------------------------------------------------------
// Kernel 2: m[b,p] = sum_k dot2(csphi[b,k], csxi[p,k]) via fma2.
// GEMM M=64(b), N=256(p), K=4096, split-K=64. grid=(4,64)=256 blocks.
// ---------------------------------------------------------------------------
__global__ __launch_bounds__(256, 3) void mgemm_kernel() {
    __shared__ __align__(16) float4 Asm[64][17];   // [b][kpair]
    __shared__ __align__(16) float2 Bsm[32][66];   // [k][p] transposed

    int p0 = blockIdx.x * 64;
    int k0 = blockIdx.y * KC;
    int tid = threadIdx.x;
    int tx = tid & 15;
    int ty = tid >> 4;

    ull acc[4][4] = {};

    const float4* A4 = (const float4*)g_csphi;
    const float4* B4 = (const float4*)g_csxi;

    for (int kk = 0; kk < KC; kk += KCH) {
        int kc4 = (k0 + kk) >> 1;
#pragma unroll
        for (int i = tid; i < 64 * 16; i += 256) {
            int r = i >> 4, c = i & 15;
            Asm[r][c] = A4[r * (NN / 2) + kc4 + c];
            float4 v = B4[(p0 + r) * (NN / 2) + kc4 + c];
            Bsm[2 * c][r] = make_float2(v.x, v.y);
            Bsm[2 * c + 1][r] = make_float2(v.z, v.w);
        }
        __syncthreads();
#pragma unroll
        for (int kp = 0; kp < 16; kp++) {
            ulonglong2 av[4];
#pragma unroll
            for (int i = 0; i < 4; i++)
                av[i] = *(const ulonglong2*)&Asm[ty * 4 + i][kp];
            ulonglong2 b0a = *(const ulonglong2*)&Bsm[2 * kp][2 * tx];
            ulonglong2 b0b = *(const ulonglong2*)&Bsm[2 * kp][2 * tx + 32];
            ulonglong2 b1a = *(const ulonglong2*)&Bsm[2 * kp + 1][2 * tx];
            ulonglong2 b1b = *(const ulonglong2*)&Bsm[2 * kp + 1][2 * tx + 32];
#pragma unroll
            for (int i = 0; i < 4; i++) {
                acc[i][0] = ffma2(av[i].x, b0a.x, acc[i][0]);
                acc[i][1] = ffma2(av[i].x, b0a.y, acc[i][1]);
                acc[i][2] = ffma2(av[i].x, b0b.x, acc[i][2]);
                acc[i][3] = ffma2(av[i].x, b0b.y, acc[i][3]);
                acc[i][0] = ffma2(av[i].y, b1a.x, acc[i][0]);
                acc[i][1] = ffma2(av[i].y, b1a.y, acc[i][1]);
                acc[i][2] = ffma2(av[i].y, b1b.x, acc[i][2]);
                acc[i][3] = ffma2(av[i].y, b1b.y, acc[i][3]);
            }
        }
        __syncthreads();
    }

    float* outp = g_mpart + blockIdx.y * (BB * PP);
    int poff[4] = {2 * tx, 2 * tx + 1, 2 * tx + 32, 2 * tx + 33};
#pragma unroll
    for (int i = 0; i < 4; i++)
#pragma unroll
        for (int j = 0; j < 4; j++) {
            float2 f = unpack2(acc[i][j]);
            outp[(ty * 4 + i) * PP + p0 + poff[j]] = f.x + f.y;
        }
}

// ---------------------------------------------------------------------------
// Kernel 3: reduce split-K partials, softmax over p (per b).
// ---------------------------------------------------------------------------
__global__ __launch_bounds__(256) void softmax_kernel() {
    __shared__ float red[256];
    int b = blockIdx.x;
    int p = threadIdx.x;

    float s = 0.f;
#pragma unroll 16
    for (int sp = 0; sp < SPLITK; sp++)
        s += g_mpart[sp * BB * PP + b * PP + p];

    float val = s * (1.0f / (float)NN);

    red[p] = val;
    __syncthreads();
    for (int off = 128; off > 0; off >>= 1) {
        if (p < off) red[p] = fmaxf(red[p], red[p + off]);
        __syncthreads();
    }
    float mx = red[0];
    __syncthreads();

    float e = expf(val - mx);
    red[p] = e;
    __syncthreads();
    for (int off = 128; off > 0; off >>= 1) {
        if (p < off) red[p] += red[p + off];
        __syncthreads();
    }
    g_w[b * PP + p] = e / red[0];
}

// ---------------------------------------------------------------------------
// Kernel 4: coupling GEMM (split-P partials), fma2, 2-D warp tiling.
//   (Wc,Ws)[sp][b,n] = sum_{p in slice} w[b,p] * (cxi,sxi)[p,n]
// Block tile 64b x 64n x 32p, 256 thr = 8 warps arranged 2(b) x 4(n).
// Warp tile 32b x 16n; lane = bg*4+ng (8 b-groups x 4 n-groups);
// thread micro 4b x 4n. Per warp-p: 2 c-LDS.128 (64B distinct) +
// 2 w-LDS.128 (128B distinct) feed 16 FFMA2 -> fma-bound ~2:1.
// W staged as [p][b] duplicated ull so 4 consecutive b = one 32B read.
// grid = (NN/64, SPLITP) = (64, 8) = 512 blocks, 3/SM.
// ---------------------------------------------------------------------------
__global__ __launch_bounds__(256, 3) void coupling_kernel() {
    __shared__ __align__(16) ull Csm[PCH][66];  // [p][n] packed (c,s), 64 used
    __shared__ __align__(16) ull Wsm[PCH][66];  // [p][b] packed (w,w), 64 used

    int n0 = blockIdx.x * 64;
    int ps0 = blockIdx.y * PCH;
    int tid = threadIdx.x;
    int warp = tid >> 5;
    int lane = tid & 31;
    int bg = lane >> 2;          // 0..7
    int ng = lane & 3;           // 0..3
    int warpB = warp & 1;        // 0..1
    int warpN = warp >> 1;       // 0..3
    int bbase = warpB * 32 + bg * 4;   // 4 consecutive b
    int nbase = warpN * 16 + ng * 4;   // 4 consecutive n (ull idx)

    const float4* X4 = (const float4*)g_csxi;

    // Stage C: 32 p rows x 64 n (as 32 float4 each)
#pragma unroll
    for (int i = tid; i < PCH * 32; i += 256) {
        int r = i >> 5, c = i & 31;
        float4 v = X4[(ps0 + r) * (NN / 2) + (n0 >> 1) + c];
        Csm[r][2 * c] = pack2(v.x, v.y);
        Csm[r][2 * c + 1] = pack2(v.z, v.w);
    }
    // Stage W transposed+duplicated: [p][b]; coalesced g_w reads (p fast)
#pragma unroll
    for (int i = tid; i < PCH * 64; i += 256) {
        int r = i & 31, c = i >> 5;  // r = p, c = b
        float w = g_w[c * PP + ps0 + r];
        Wsm[r][c] = pack2(w, w);
    }
    __syncthreads();

    ull acc[4][4] = {};  // [b i][n j]
#pragma unroll
    for (int p = 0; p < PCH; p++) {
        ulonglong2 c0 = *(const ulonglong2*)&Csm[p][nbase];
        ulonglong2 c1 = *(const ulonglong2*)&Csm[p][nbase + 2];
        ulonglong2 w0 = *(const ulonglong2*)&Wsm[p][bbase];
        ulonglong2 w1 = *(const ulonglong2*)&Wsm[p][bbase + 2];
        acc[0][0] = ffma2(w0.x, c0.x, acc[0][0]);
        acc[0][1] = ffma2(w0.x, c0.y, acc[0][1]);
        acc[0][2] = ffma2(w0.x, c1.x, acc[0][2]);
        acc[0][3] = ffma2(w0.x, c1.y, acc[0][3]);
        acc[1][0] = ffma2(w0.y, c0.x, acc[1][0]);
        acc[1][1] = ffma2(w0.y, c0.y, acc[1][1]);
        acc[1][2] = ffma2(w0.y, c1.x, acc[1][2]);
        acc[1][3] = ffma2(w0.y, c1.y, acc[1][3]);
        acc[2][0] = ffma2(w1.x, c0.x, acc[2][0]);
        acc[2][1] = ffma2(w1.x, c0.y, acc[2][1]);
        acc[2][2] = ffma2(w1.x, c1.x, acc[2][2]);
        acc[2][3] = ffma2(w1.x, c1.y, acc[2][3]);
        acc[3][0] = ffma2(w1.y, c0.x, acc[3][0]);
        acc[3][1] = ffma2(w1.y, c0.y, acc[3][1]);
        acc[3][2] = ffma2(w1.y, c1.x, acc[3][2]);
        acc[3][3] = ffma2(w1.y, c1.y, acc[3][3]);
    }

    ull* outp = g_cpart[blockIdx.y];
#pragma unroll
    for (int i = 0; i < 4; i++) {
        int base = (bbase + i) * NN + n0 + nbase;  // 32B contiguous per thread
        *(ulonglong2*)&outp[base] = make_ulonglong2(acc[i][0], acc[i][1]);
        *(ulonglong2*)&outp[base + 2] = make_ulonglong2(acc[i][2], acc[i][3]);
    }
}

// ---------------------------------------------------------------------------
// Kernel 5: combine split-P partials + anchor epilogue.
//   out[b,n] = sphi*Wc - cphi*Ws + A*(sin(wt)*cphi - cos(wt)*sphi)
// ---------------------------------------------------------------------------
__global__ __launch_bounds__(256) void finish_kernel(const float* __restrict__ t,
                                                     float* __restrict__ out) {
    int i = blockIdx.x * 256 + threadIdx.x;  // pair index over BB*NN/2

    float2 a0 = make_float2(0.f, 0.f);
    float2 a1 = make_float2(0.f, 0.f);
#pragma unroll
    for (int sp = 0; sp < SPLITP; sp++) {
        ulonglong2 v = *(const ulonglong2*)&g_cpart[sp][2 * i];
        float2 f0 = unpack2(v.x), f1 = unpack2(v.y);
        a0.x += f0.x; a0.y += f0.y;
        a1.x += f1.x; a1.y += f1.y;
    }

    float tv = t[0];
    double sd, cd;
    sincos((double)(1256.6370614359172f * tv), &sd, &cd);
    float st = (float)sd, ct = (float)cd;

    const float4* P4 = (const float4*)g_csphi;
    float4 cs = P4[i];  // (cphi0, sphi0, cphi1, sphi1)

    float2 o;
    o.x = cs.y * a0.x - cs.x * a0.y + 0.08f * (st * cs.x - ct * cs.y);
    o.y = cs.w * a1.x - cs.z * a1.y + 0.08f * (st * cs.z - ct * cs.w);
    *(float2*)&out[2 * i] = o;
}

// ---------------------------------------------------------------------------
extern "C" void kernel_launch(void* const* d_in, const int* in_sizes, int n_in,
                              void* d_out, int out_size) {
    const float* t = nullptr;
    const float* phi = nullptr;
    const float* xi = nullptr;
    for (int i = 0; i < n_in; i++) {
        if (in_sizes[i] == 1) t = (const float*)d_in[i];
        else if (in_sizes[i] == BB * NN) phi = (const float*)d_in[i];
        else if (in_sizes[i] == PP * NN) xi = (const float*)d_in[i];
    }
    float* out = (float*)d_out;

    trig_kernel<<<((BB + PP) * NN + 255) / 256, 256>>>(phi, xi);
    mgemm_kernel<<<dim3(PP / 64, SPLITK), 256>>>();
    softmax_kernel<<<BB, 256>>>();
    coupling_kernel<<<dim3(NN / 64, SPLITP), 256>>>();
    finish_kernel<<<(BB * NN / 2) / 256, 256>>>(t, out);
}

// round 15
// speedup vs baseline: 1.3080x; 1.3080x over previous
#include <cuda_runtime.h>
#include <math.h>

#define BB 64
#define PP 256
#define NN 4096
#define SPLITK 64
#define KC (NN / SPLITK)   // 64 (two 32-k chunks per block)
#define KCH 32
#define SPLITP 8
#define PCH (PP / SPLITP)  // 32 (one chunk per block)

typedef unsigned long long ull;

// Interleaved (cos, sin) tables
__device__ __align__(16) float2 g_csphi[BB * NN];
__device__ __align__(16) float2 g_csxi[PP * NN];
__device__ float g_mpart[SPLITK * BB * PP];
__device__ float g_w[BB * PP];
__device__ __align__(16) ull g_cpart[SPLITP][BB * NN];  // packed (Wc, Ws) partials
__device__ float2 g_anchor;  // (sin(w*t), cos(w*t)) computed once

// Packed fp32x2 FMA (Blackwell FFMA2)
__device__ __forceinline__ ull ffma2(ull a, ull b, ull c) {
    ull d;
    asm("fma.rn.f32x2 %0, %1, %2, %3;" : "=l"(d) : "l"(a), "l"(b), "l"(c));
    return d;
}
__device__ __forceinline__ ull pack2(float x, float y) {
    ull r; asm("mov.b64 %0, {%1, %2};" : "=l"(r) : "f"(x), "f"(y)); return r;
}
__device__ __forceinline__ float2 unpack2(ull v) {
    float2 f; asm("mov.b64 {%0, %1}, %2;" : "=f"(f.x), "=f"(f.y) : "l"(v)); return f;
}

// ---------------------------------------------------------------------------
// Kernel 1: phi trig table only (xi trig is fused into mgemm), plus the
// scalar anchor sincos(omega*t) computed by ONE thread (fp64 for accuracy
// at arg ~1256 rad; previously this ran in all 131K finish threads).
// ---------------------------------------------------------------------------
__global__ __launch_bounds__(256) void trig_kernel(const float* __restrict__ phi,
                                                   const float* __restrict__ t) {
    int i = blockIdx.x * 256 + threadIdx.x;
    if (i == 0) {
        double sd, cd;
        sincos((double)(1256.6370614359172f * t[0]), &sd, &cd);
        g_anchor = make_float2((float)sd, (float)cd);
    }
    if (i < BB * NN) {
        float s, c;
        __sincosf(phi[i], &s, &c);
        g_csphi[i] = make_float2(c, s);
    }
}

// ---------------------------------------------------------------------------
// Kernel 2: m[b,p] = sum_k dot2(csphi[b,k], csxi[p,k]) via fma2.
// xi trig FUSED: loads raw xi (half the bytes of the (c,s) table), does
// __sincosf at stage time (MUFU pipe overlaps fma), stores csxi to global
// for coupling. Each (p,k) is staged by exactly one block -> writes disjoint.
// GEMM M=64(b), N=256(p), K=4096, split-K=64. grid=(4,64)=256 blocks.
// ---------------------------------------------------------------------------
__global__ __launch_bounds__(256, 3) void mgemm_kernel(const float* __restrict__ xi) {
    __shared__ __align__(16) float4 Asm[64][17];   // [b][kpair] (c,s,c,s)
    __shared__ __align__(16) float2 Bsm[32][66];   // [k][p] transposed (c,s)

    int p0 = blockIdx.x * 64;
    int k0 = blockIdx.y * KC;
    int tid = threadIdx.x;
    int tx = tid & 15;
    int ty = tid >> 4;

    ull acc[4][4] = {};

    const float4* A4 = (const float4*)g_csphi;
    const float4* X4 = (const float4*)xi;
    float4* CS4 = (float4*)g_csxi;

    for (int kk = 0; kk < KC; kk += KCH) {
        int kc = k0 + kk;
        // Stage A (precomputed phi table)
        int kc4 = kc >> 1;
#pragma unroll
        for (int i = tid; i < 64 * 16; i += 256) {
            int r = i >> 4, c = i & 15;
            Asm[r][c] = A4[r * (NN / 2) + kc4 + c];
        }
        // Stage B: raw xi -> sincos -> smem (transposed) + global csxi
#pragma unroll
        for (int i = tid; i < 64 * 8; i += 256) {
            int r = i >> 3, c4 = i & 7;          // r = p row, c4 = float4 col
            float4 x = X4[((p0 + r) * NN + kc) / 4 + c4];
            float s0, c0, s1, c1, s2, c2, s3, c3;
            __sincosf(x.x, &s0, &c0);
            __sincosf(x.y, &s1, &c1);
            __sincosf(x.z, &s2, &c2);
            __sincosf(x.w, &s3, &c3);
            int kb = 4 * c4;
            Bsm[kb + 0][r] = make_float2(c0, s0);
            Bsm[kb + 1][r] = make_float2(c1, s1);
            Bsm[kb + 2][r] = make_float2(c2, s2);
            Bsm[kb + 3][r] = make_float2(c3, s3);
            int gbase = ((p0 + r) * NN + kc) / 2 + 2 * c4;  // float4 index
            CS4[gbase] = make_float4(c0, s0, c1, s1);
            CS4[gbase + 1] = make_float4(c2, s2, c3, s3);
        }
        __syncthreads();
#pragma unroll
        for (int kp = 0; kp < 16; kp++) {
            ulonglong2 av[4];
#pragma unroll
            for (int i = 0; i < 4; i++)
                av[i] = *(const ulonglong2*)&Asm[ty * 4 + i][kp];
            ulonglong2 b0a = *(const ulonglong2*)&Bsm[2 * kp][2 * tx];
            ulonglong2 b0b = *(const ulonglong2*)&Bsm[2 * kp][2 * tx + 32];
            ulonglong2 b1a = *(const ulonglong2*)&Bsm[2 * kp + 1][2 * tx];
            ulonglong2 b1b = *(const ulonglong2*)&Bsm[2 * kp + 1][2 * tx + 32];
#pragma unroll
            for (int i = 0; i < 4; i++) {
                acc[i][0] = ffma2(av[i].x, b0a.x, acc[i][0]);
                acc[i][1] = ffma2(av[i].x, b0a.y, acc[i][1]);
                acc[i][2] = ffma2(av[i].x, b0b.x, acc[i][2]);
                acc[i][3] = ffma2(av[i].x, b0b.y, acc[i][3]);
                acc[i][0] = ffma2(av[i].y, b1a.x, acc[i][0]);
                acc[i][1] = ffma2(av[i].y, b1a.y, acc[i][1]);
                acc[i][2] = ffma2(av[i].y, b1b.x, acc[i][2]);
                acc[i][3] = ffma2(av[i].y, b1b.y, acc[i][3]);
            }
        }
        __syncthreads();
    }

    float* outp = g_mpart + blockIdx.y * (BB * PP);
    int poff[4] = {2 * tx, 2 * tx + 1, 2 * tx + 32, 2 * tx + 33};
#pragma unroll
    for (int i = 0; i < 4; i++)
#pragma unroll
        for (int j = 0; j < 4; j++) {
            float2 f = unpack2(acc[i][j]);
            outp[(ty * 4 + i) * PP + p0 + poff[j]] = f.x + f.y;
        }
}

// ---------------------------------------------------------------------------
// Kernel 3: reduce split-K partials, softmax over p (per b).
// ---------------------------------------------------------------------------
__global__ __launch_bounds__(256) void softmax_kernel() {
    __shared__ float red[256];
    int b = blockIdx.x;
    int p = threadIdx.x;

    float s = 0.f;
#pragma unroll 16
    for (int sp = 0; sp < SPLITK; sp++)
        s += g_mpart[sp * BB * PP + b * PP + p];

    float val = s * (1.0f / (float)NN);

    red[p] = val;
    __syncthreads();
    for (int off = 128; off > 0; off >>= 1) {
        if (p < off) red[p] = fmaxf(red[p], red[p + off]);
        __syncthreads();
    }
    float mx = red[0];
    __syncthreads();

    float e = expf(val - mx);
    red[p] = e;
    __syncthreads();
    for (int off = 128; off > 0; off >>= 1) {
        if (p < off) red[p] += red[p + off];
        __syncthreads();
    }
    g_w[b * PP + p] = e / red[0];
}

// ---------------------------------------------------------------------------
// Kernel 4: coupling GEMM (split-P partials) — R11-exact (measured 13.0us).
//   (Wc,Ws)[sp][b,n] = sum_{p in slice} w[b,p] * (cxi,sxi)[p,n]
// Tile ALL 64b x 64n x 32p per block, 256 thr (16 tx x 16 ty), micro 4b x 4n.
// Contiguous half-warp Csm reads; W pre-duplicated; (256,4) -> one wave.
// grid = (NN/64, SPLITP) = (64, 8) = 512 blocks.
// ---------------------------------------------------------------------------
__global__ __launch_bounds__(256, 4) void coupling_kernel() {
    __shared__ __align__(16) float2 Csm[PCH][66];  // [p][n] (c,s)
    __shared__ __align__(16) ull Wsm2[64][33];     // [b][p] pre-duplicated (w,w)

    int n0 = blockIdx.x * 64;
    int ps0 = blockIdx.y * PCH;
    int tid = threadIdx.x;
    int tx = tid & 15;   // n-thread
    int ty = tid >> 4;   // b-thread: b = 4*ty .. +3

    const float4* X4 = (const float4*)g_csxi;

    // Stage C: 32 p x 32 float4 (= 64 n as (c,s) pairs)
#pragma unroll
    for (int i = tid; i < PCH * 32; i += 256) {
        int r = i >> 5, c = i & 31;
        float4 v = X4[(ps0 + r) * (NN / 2) + (n0 >> 1) + c];
        Csm[r][2 * c] = make_float2(v.x, v.y);
        Csm[r][2 * c + 1] = make_float2(v.z, v.w);
    }
    // Stage W duplicated: 64 b x 32 p
#pragma unroll
    for (int i = tid; i < 64 * PCH; i += 256) {
        int r = i >> 5, c = i & 31;
        float w = g_w[r * PP + ps0 + c];
        Wsm2[r][c] = pack2(w, w);
    }
    __syncthreads();

    ull acc[4][4] = {};
#pragma unroll
    for (int p = 0; p < PCH; p++) {
        ulonglong2 c01 = *(const ulonglong2*)&Csm[p][2 * tx];       // n0+2tx, +1
        ulonglong2 c23 = *(const ulonglong2*)&Csm[p][2 * tx + 32];  // n0+32+2tx, +1
        ull w0 = Wsm2[4 * ty + 0][p];
        ull w1 = Wsm2[4 * ty + 1][p];
        ull w2 = Wsm2[4 * ty + 2][p];
        ull w3 = Wsm2[4 * ty + 3][p];
        acc[0][0] = ffma2(w0, c01.x, acc[0][0]);
        acc[0][1] = ffma2(w0, c01.y, acc[0][1]);
        acc[0][2] = ffma2(w0, c23.x, acc[0][2]);
        acc[0][3] = ffma2(w0, c23.y, acc[0][3]);
        acc[1][0] = ffma2(w1, c01.x, acc[1][0]);
        acc[1][1] = ffma2(w1, c01.y, acc[1][1]);
        acc[1][2] = ffma2(w1, c23.x, acc[1][2]);
        acc[1][3] = ffma2(w1, c23.y, acc[1][3]);
        acc[2][0] = ffma2(w2, c01.x, acc[2][0]);
        acc[2][1] = ffma2(w2, c01.y, acc[2][1]);
        acc[2][2] = ffma2(w2, c23.x, acc[2][2]);
        acc[2][3] = ffma2(w2, c23.y, acc[2][3]);
        acc[3][0] = ffma2(w3, c01.x, acc[3][0]);
        acc[3][1] = ffma2(w3, c01.y, acc[3][1]);
        acc[3][2] = ffma2(w3, c23.x, acc[3][2]);
        acc[3][3] = ffma2(w3, c23.y, acc[3][3]);
    }

    ull* outp = g_cpart[blockIdx.y];
#pragma unroll
    for (int i = 0; i < 4; i++) {
        int base = (4 * ty + i) * NN + n0 + 2 * tx;  // coalesced 16B/lane
        *(ulonglong2*)&outp[base] = make_ulonglong2(acc[i][0], acc[i][1]);
        *(ulonglong2*)&outp[base + 32] = make_ulonglong2(acc[i][2], acc[i][3]);
    }
}

// ---------------------------------------------------------------------------
// Kernel 5: combine split-P partials + anchor epilogue (scalar anchor
// preloaded from g_anchor — no per-thread fp64 sincos).
//   out[b,n] = sphi*Wc - cphi*Ws + A*(st*cphi - ct*sphi)
// ---------------------------------------------------------------------------
__global__ __launch_bounds__(256) void finish_kernel(float* __restrict__ out) {
    int i = blockIdx.x * 256 + threadIdx.x;  // pair index over BB*NN/2

    float2 anc = g_anchor;
    float st = anc.x, ct = anc.y;

    float2 a0 = make_float2(0.f, 0.f);
    float2 a1 = make_float2(0.f, 0.f);
#pragma unroll
    for (int sp = 0; sp < SPLITP; sp++) {
        ulonglong2 v = *(const ulonglong2*)&g_cpart[sp][2 * i];
        float2 f0 = unpack2(v.x), f1 = unpack2(v.y);
        a0.x += f0.x; a0.y += f0.y;
        a1.x += f1.x; a1.y += f1.y;
    }

    const float4* P4 = (const float4*)g_csphi;
    float4 cs = P4[i];  // (cphi0, sphi0, cphi1, sphi1)

    float2 o;
    o.x = cs.y * a0.x - cs.x * a0.y + 0.08f * (st * cs.x - ct * cs.y);
    o.y = cs.w * a1.x - cs.z * a1.y + 0.08f * (st * cs.z - ct * cs.w);
    *(float2*)&out[2 * i] = o;
}

// ---------------------------------------------------------------------------
extern "C" void kernel_launch(void* const* d_in, const int* in_sizes, int n_in,
                              void* d_out, int out_size) {
    const float* t = nullptr;
    const float* phi = nullptr;
    const float* xi = nullptr;
    for (int i = 0; i < n_in; i++) {
        if (in_sizes[i] == 1) t = (const float*)d_in[i];
        else if (in_sizes[i] == BB * NN) phi = (const float*)d_in[i];
        else if (in_sizes[i] == PP * NN) xi = (const float*)d_in[i];
    }
    float* out = (float*)d_out;

    trig_kernel<<<(BB * NN) / 256, 256>>>(phi, t);
    mgemm_kernel<<<dim3(PP / 64, SPLITK), 256>>>(xi);
    softmax_kernel<<<BB, 256>>>();
    coupling_kernel<<<dim3(NN / 64, SPLITP), 256>>>();
    finish_kernel<<<(BB * NN / 2) / 256, 256>>>(out);
}